// round 3
// baseline (speedup 1.0000x reference)
#include <cuda_runtime.h>
#include <math.h>

#define BZ   4
#define LSEQ 2048
#define DM   1024
#define DI   2048
#define E2   4096
#define RNK  64
#define NST  16
#define XDB  96

// ---------------- scratch (static device globals; no runtime alloc) ----------------
// Aliasing plan (stream-ordered launches make lifetimes disjoint):
//   g_xz   [b][e][l]  : written step1, read steps 2/2b, then dead.
//                       first half reused as delta[b][l][d] in step 4/5.
//   g_zt   [b][l][d]  : silu(z); read in scan; scan output y overwrites in place.
__device__ float g_xz  [(size_t)BZ * E2  * LSEQ];   // 128 MB (also: delta after step 3)
__device__ float g_xc  [(size_t)BZ * LSEQ * DI];    //  64 MB gated conv output [b][l][d]
__device__ float g_zt  [(size_t)BZ * LSEQ * DI];    //  64 MB silu(z) -> y (in place)
__device__ float g_xdbl[(size_t)BZ * LSEQ * XDB];   //   3 MB dt_low|B|C

#define BUF_EXT  0
#define BUF_XZ   1
#define BUF_XC   2
#define BUF_XDBL 3
#define BUF_DLT  4   // alias: first BZ*LSEQ*DI floats of g_xz
#define BUF_ZT   5

__device__ __forceinline__ const float* resolve_c(int id, const float* ext) {
    switch (id) {
        case BUF_XZ:   return g_xz;
        case BUF_XC:   return g_xc;
        case BUF_XDBL: return g_xdbl;
        case BUF_DLT:  return g_xz;     // alias
        case BUF_ZT:   return g_zt;
        default:       return ext;
    }
}
__device__ __forceinline__ float* resolve_m(int id, float* ext) {
    switch (id) {
        case BUF_XZ:   return g_xz;
        case BUF_XC:   return g_xc;
        case BUF_XDBL: return g_xdbl;
        case BUF_DLT:  return g_xz;     // alias
        case BUF_ZT:   return g_zt;
        default:       return ext;
    }
}

// ---------------- generic C = A * B^T  (both operands K-contiguous) ----------------
// C[m,n] = sum_k A[m*lda+k] * B[n*ldb+k];  z-batched via strides.
// act==1: softplus(c + bias[n])
__global__ void __launch_bounds__(256) gemm_tn_kernel(
    const float* __restrict__ Aext, int aid, int lda, long sA,
    const float* __restrict__ Bext, int bid, int ldb, long sB,
    float*       __restrict__ Cext, int cid, int ldc, long sC,
    int M, int N, int K,
    const float* __restrict__ bias, int act)
{
    const float* A = resolve_c(aid, Aext);
    const float* B = resolve_c(bid, Bext);
    float*       C = resolve_m(cid, Cext);

    __shared__ float As[8][128];
    __shared__ float Bs[8][128];
    const int bn0 = blockIdx.x * 128;
    const int bm0 = blockIdx.y * 128;
    const float* Ab = A + (long)blockIdx.z * sA;
    const float* Bb = B + (long)blockIdx.z * sB;
    float*       Cb = C + (long)blockIdx.z * sC;

    const int tid  = threadIdx.x;
    const int tx   = tid & 15;        // 16 n-groups
    const int ty   = tid >> 4;        // 16 m-groups
    const int lrow = tid >> 1;        // 0..127
    const int lc4  = (tid & 1) * 4;   // 0 or 4

    float acc[8][8];
#pragma unroll
    for (int i = 0; i < 8; i++)
#pragma unroll
        for (int j = 0; j < 8; j++) acc[i][j] = 0.f;

    const float* Aptr = Ab + (long)(bm0 + lrow) * lda + lc4;
    const float* Bptr = Bb + (long)(bn0 + lrow) * ldb + lc4;
    const bool bvalid = (bn0 + lrow) < N;

    for (int k0 = 0; k0 < K; k0 += 8) {
        float4 av = *(const float4*)(Aptr + k0);
        float4 bv = make_float4(0.f, 0.f, 0.f, 0.f);
        if (bvalid) bv = *(const float4*)(Bptr + k0);
        __syncthreads();
        As[lc4 + 0][lrow] = av.x; As[lc4 + 1][lrow] = av.y;
        As[lc4 + 2][lrow] = av.z; As[lc4 + 3][lrow] = av.w;
        Bs[lc4 + 0][lrow] = bv.x; Bs[lc4 + 1][lrow] = bv.y;
        Bs[lc4 + 2][lrow] = bv.z; Bs[lc4 + 3][lrow] = bv.w;
        __syncthreads();
#pragma unroll
        for (int kk = 0; kk < 8; kk++) {
            float a[8], bb[8];
#pragma unroll
            for (int i = 0; i < 8; i++) a[i]  = As[kk][ty * 8 + i];
#pragma unroll
            for (int j = 0; j < 8; j++) bb[j] = Bs[kk][tx * 8 + j];
#pragma unroll
            for (int i = 0; i < 8; i++)
#pragma unroll
                for (int j = 0; j < 8; j++)
                    acc[i][j] = fmaf(a[i], bb[j], acc[i][j]);
        }
    }

#pragma unroll
    for (int i = 0; i < 8; i++) {
        const long row = bm0 + ty * 8 + i;
#pragma unroll
        for (int j = 0; j < 8; j++) {
            const int n = bn0 + tx * 8 + j;
            if (n < N) {
                float v = acc[i][j];
                if (act == 1) {
                    v += bias[n];
                    v = (v > 20.f) ? v : log1pf(expf(v));
                }
                Cb[row * ldc + n] = v;
            }
        }
    }
}

// ---------------- depthwise causal convs (k=4, dil 1 & 2) + silu + gate mix --------
// reads x = g_xz[b][d][l] (d<2048), writes g_xc[b][l][d] (transposed)
__global__ void __launch_bounds__(256) conv_gate_kernel(
    const float* __restrict__ w1, const float* __restrict__ b1,
    const float* __restrict__ w2, const float* __restrict__ b2,
    const float* __restrict__ gates)
{
    __shared__ float xs[32][73];
    const int l0 = blockIdx.x * 64;
    const int d0 = blockIdx.y * 32;
    const int b  = blockIdx.z;
    const int tid = threadIdx.x;

    for (int i = tid; i < 32 * 70; i += 256) {
        const int r = i / 70, c = i % 70;
        const int gl = l0 - 6 + c;
        float v = 0.f;
        if (gl >= 0) v = g_xz[((size_t)(b * E2 + d0 + r)) * LSEQ + gl];
        xs[r][c] = v;
    }
    __syncthreads();

    const float e0 = expf(gates[0]), e1 = expf(gates[1]);
    const float g0 = e0 / (e0 + e1), g1 = e1 / (e0 + e1);

    const int dl = tid & 31;
    const int lg = tid >> 5;
    const int d  = d0 + dl;
    const float w10 = w1[d*4+0], w11 = w1[d*4+1], w12 = w1[d*4+2], w13 = w1[d*4+3];
    const float w20 = w2[d*4+0], w21 = w2[d*4+1], w22 = w2[d*4+2], w23 = w2[d*4+3];
    const float b1v = b1[d], b2v = b2[d];

#pragma unroll
    for (int q = 0; q < 8; q++) {
        const int lloc = lg * 8 + q;
        const int p = lloc + 6;
        float v1 = b1v + w10*xs[dl][p-3] + w11*xs[dl][p-2] + w12*xs[dl][p-1] + w13*xs[dl][p];
        v1 = v1 / (1.f + __expf(-v1));
        float v2 = b2v + w20*xs[dl][p-6] + w21*xs[dl][p-4] + w22*xs[dl][p-2] + w23*xs[dl][p];
        v2 = v2 / (1.f + __expf(-v2));
        g_xc[((size_t)b * LSEQ + (l0 + lloc)) * DI + d] = g0 * v1 + g1 * v2;
    }
}

// ---------------- z: transpose + silu -> g_zt[b][l][d] ----------------
__global__ void __launch_bounds__(256) zt_kernel()
{
    __shared__ float t[32][33];
    const int l0 = blockIdx.x * 32, d0 = blockIdx.y * 32, b = blockIdx.z;
    const int tx = threadIdx.x & 31, ty = threadIdx.x >> 5;   // 32 x 8
#pragma unroll
    for (int i = 0; i < 4; i++) {
        const int dr = ty + i * 8;
        t[dr][tx] = g_xz[((size_t)(b * E2 + DI + d0 + dr)) * LSEQ + l0 + tx];
    }
    __syncthreads();
#pragma unroll
    for (int i = 0; i < 4; i++) {
        const int lr = ty + i * 8;
        const float v = t[tx][lr];
        g_zt[((size_t)b * LSEQ + (l0 + lr)) * DI + d0 + tx] = v / (1.f + __expf(-v));
    }
}

// ---------------- selective scan (+ D skip + silu(z) gating) ----------------
// one thread per (b, d); 16 states in registers; B/C staged in smem per 32-step chunk
// y overwrites g_zt in place (each idx: read zt, then write y).
__global__ void __launch_bounds__(64) scan_kernel(
    const float* __restrict__ A_log,
    const float* __restrict__ Dp)
{
    __shared__ float Bs[32][16];
    __shared__ float Cs[32][16];
    const int b = blockIdx.y;
    const int d = blockIdx.x * 64 + threadIdx.x;
    const float* __restrict__ dltp = g_xz;   // delta alias

    float A[NST], h[NST];
#pragma unroll
    for (int n = 0; n < NST; n++) {
        A[n] = -expf(A_log[d * NST + n]);
        h[n] = 0.f;
    }
    const float Dv = Dp[d];

    for (int t0 = 0; t0 < LSEQ; t0 += 32) {
        __syncthreads();
        for (int i = threadIdx.x; i < 32 * 32; i += 64) {
            const int tl = i >> 5, c = i & 31;
            const float v = g_xdbl[((size_t)b * LSEQ + t0 + tl) * XDB + RNK + c];
            if (c < 16) Bs[tl][c] = v;
            else        Cs[tl][c - 16] = v;
        }
        __syncthreads();
        for (int tl = 0; tl < 32; tl++) {
            const size_t idx = ((size_t)b * LSEQ + t0 + tl) * DI + d;
            const float dlt = dltp[idx];
            const float xv  = g_xc[idx];
            const float dbx = dlt * xv;
            float yy = 0.f;
#pragma unroll
            for (int n = 0; n < NST; n++) {
                const float dA = __expf(dlt * A[n]);
                h[n] = fmaf(h[n], dA, dbx * Bs[tl][n]);
                yy   = fmaf(h[n], Cs[tl][n], yy);
            }
            g_zt[idx] = (yy + Dv * xv) * g_zt[idx];   // y in place over silu(z)
        }
    }
}

// ---------------- launch (kernel launches ONLY) ----------------
extern "C" void kernel_launch(void* const* d_in, const int* in_sizes, int n_in,
                              void* d_out, int out_size)
{
    (void)in_sizes; (void)n_in; (void)out_size;
    const float* hs    = (const float*)d_in[0];
    const float* W_in  = (const float*)d_in[1];
    const float* cw1   = (const float*)d_in[2];
    const float* cb1   = (const float*)d_in[3];
    const float* cw2   = (const float*)d_in[4];
    const float* cb2   = (const float*)d_in[5];
    const float* gts   = (const float*)d_in[6];
    const float* W_x   = (const float*)d_in[7];
    const float* W_dt  = (const float*)d_in[8];
    const float* b_dt  = (const float*)d_in[9];
    const float* A_log = (const float*)d_in[10];
    const float* Dp    = (const float*)d_in[11];
    const float* W_out = (const float*)d_in[12];
    float* out = (float*)d_out;

    // 1) xz[b][e][l] = W_in[e,:] . hs[b,l,:]
    gemm_tn_kernel<<<dim3(LSEQ / 128, E2 / 128, BZ), 256>>>(
        W_in, BUF_EXT, DM, 0L,
        hs,   BUF_EXT, DM, (long)LSEQ * DM,
        nullptr, BUF_XZ, LSEQ, (long)E2 * LSEQ,
        E2, LSEQ, DM, nullptr, 0);

    // 2) depthwise convs + silu + gate mix -> xc[b][l][d]
    conv_gate_kernel<<<dim3(LSEQ / 64, DI / 32, BZ), 256>>>(
        cw1, cb1, cw2, cb2, gts);

    // 2b) silu(z) transpose -> zt[b][l][d]
    zt_kernel<<<dim3(LSEQ / 32, DI / 32, BZ), 256>>>();

    // 3) x_dbl[b*l, 96] = xc . W_x^T   (g_xz now dead; safe to reuse)
    gemm_tn_kernel<<<dim3(1, (BZ * LSEQ) / 128, 1), 256>>>(
        nullptr, BUF_XC, DI, 0L,
        W_x,     BUF_EXT, DI, 0L,
        nullptr, BUF_XDBL, XDB, 0L,
        BZ * LSEQ, XDB, DI, nullptr, 0);

    // 4) delta = softplus(dt_low . W_dt^T + b_dt)  -> alias into g_xz
    gemm_tn_kernel<<<dim3(DI / 128, (BZ * LSEQ) / 128, 1), 256>>>(
        nullptr, BUF_XDBL, XDB, 0L,
        W_dt,    BUF_EXT,  RNK, 0L,
        nullptr, BUF_DLT,  DI, 0L,
        BZ * LSEQ, DI, RNK, b_dt, 1);

    // 5) selective scan + D skip + silu(z) gating -> y (in place over g_zt)
    scan_kernel<<<dim3(DI / 64, BZ), 64>>>(A_log, Dp);

    // 6) out[b*l, o] = y . W_out^T
    gemm_tn_kernel<<<dim3(DM / 128, (BZ * LSEQ) / 128, 1), 256>>>(
        nullptr, BUF_ZT,  DI, 0L,
        W_out,   BUF_EXT, DI, 0L,
        out,     BUF_EXT, DM, 0L,
        BZ * LSEQ, DM, DI, nullptr, 0);
}

// round 6
// speedup vs baseline: 1.4523x; 1.4523x over previous
#include <cuda_runtime.h>
#include <cuda_bf16.h>
#include <math.h>
#include <stdint.h>

#define BZ   4
#define LSEQ 2048
#define DM   1024
#define DI   2048
#define E2   4096
#define RNK  64
#define NST  16
#define XDB  96

// ================= fp32 scratch =================
__device__ float g_xz  [(size_t)BZ * E2  * LSEQ];  // xz [b][e][l]; first 64MB reused as delta [b*l][d]
__device__ float g_xc  [(size_t)BZ * LSEQ * DI];   // gated conv out [b][l][d]
__device__ float g_zt  [(size_t)BZ * LSEQ * DI];   // silu(z) -> y in place
__device__ float g_xdbl[(size_t)BZ * LSEQ * XDB];  // dt_low|B|C

// ================= bf16 hi/lo scratch =================
__device__ __nv_bfloat16 g_Win_h [E2 * DM],  g_Win_l [E2 * DM];
__device__ __nv_bfloat16 g_hs_h  [(size_t)BZ * LSEQ * DM], g_hs_l[(size_t)BZ * LSEQ * DM];
__device__ __nv_bfloat16 g_Wx_h  [XDB * DI], g_Wx_l  [XDB * DI];
__device__ __nv_bfloat16 g_Wdt_h [DI * RNK], g_Wdt_l [DI * RNK];
__device__ __nv_bfloat16 g_Wout_h[DM * DI],  g_Wout_l[DM * DI];
__device__ __nv_bfloat16 g_xc_h  [(size_t)BZ * LSEQ * DI], g_xc_l[(size_t)BZ * LSEQ * DI];
__device__ __nv_bfloat16 g_xdb_h [(size_t)BZ * LSEQ * XDB], g_xdb_l[(size_t)BZ * LSEQ * XDB];
__device__ __nv_bfloat16 g_y_h   [(size_t)BZ * LSEQ * DI], g_y_l [(size_t)BZ * LSEQ * DI];

// pair ids
#define PB_WIN  0
#define PB_HS   1
#define PB_WX   2
#define PB_WDT  3
#define PB_WOUT 4
#define PB_XC   5
#define PB_XDBL 6
#define PB_Y    7

__device__ __forceinline__ void resolve_pair(int id, const __nv_bfloat16*& h, const __nv_bfloat16*& l) {
    switch (id) {
        case PB_WIN:  h = g_Win_h;  l = g_Win_l;  break;
        case PB_HS:   h = g_hs_h;   l = g_hs_l;   break;
        case PB_WX:   h = g_Wx_h;   l = g_Wx_l;   break;
        case PB_WDT:  h = g_Wdt_h;  l = g_Wdt_l;  break;
        case PB_WOUT: h = g_Wout_h; l = g_Wout_l; break;
        case PB_XC:   h = g_xc_h;   l = g_xc_l;   break;
        case PB_XDBL: h = g_xdb_h;  l = g_xdb_l;  break;
        default:      h = g_y_h;    l = g_y_l;    break;
    }
}
__device__ __forceinline__ void resolve_pair_m(int id, __nv_bfloat16*& h, __nv_bfloat16*& l) {
    switch (id) {
        case PB_WIN:  h = g_Win_h;  l = g_Win_l;  break;
        case PB_HS:   h = g_hs_h;   l = g_hs_l;   break;
        case PB_WX:   h = g_Wx_h;   l = g_Wx_l;   break;
        case PB_WDT:  h = g_Wdt_h;  l = g_Wdt_l;  break;
        case PB_WOUT: h = g_Wout_h; l = g_Wout_l; break;
        case PB_XC:   h = g_xc_h;   l = g_xc_l;   break;
        case PB_XDBL: h = g_xdb_h;  l = g_xdb_l;  break;
        default:      h = g_y_h;    l = g_y_l;    break;
    }
}

// bf16 mma: D += A*B, A row-major m16k16, B col-major k16n8, fp32 acc
#define MMA_BF16(d, a, b) \
    asm volatile("mma.sync.aligned.m16n8k16.row.col.f32.bf16.bf16.f32 " \
        "{%0,%1,%2,%3}, {%4,%5,%6,%7}, {%8,%9}, {%0,%1,%2,%3};" \
        : "+f"((d)[0]), "+f"((d)[1]), "+f"((d)[2]), "+f"((d)[3]) \
        : "r"((a)[0]), "r"((a)[1]), "r"((a)[2]), "r"((a)[3]), \
          "r"((b)[0]), "r"((b)[1]))

// ================= warp-MMA GEMM  C = A * B^T  (hi/lo split, 3 MMAs) =================
// A: M x K (K-contig, ld=lda), pair aid. Block tile 128(M) x 64(N), K staged 32.
// B: N x K (K-contig, ld=ldb), pair bid. N guarded by Ncols.
// C: fp32 row-major (ld=ldc). cid: 0=ext, 1=g_xz, 2=g_xdbl.
// epi: 0 plain, 1 softplus(v + bias[col]).
// Requires: M % 128 == 0, K % 32 == 0. grid (ceil(N/64), M/128, batch), 256 thr.
__global__ void __launch_bounds__(256) mm_gemm(
    int aid, int lda, long long strA,
    int bid, int ldb, long long strB,
    float* __restrict__ Cext, int cid, int ldc, long long strC,
    int K, int Ncols, const float* __restrict__ bias, int epi)
{
    // smem words: Ah[128][20] @0, Al @2560, Bh[64][20] @5120, Bl @6400 (pad 32->40 bf16/row)
    __shared__ __align__(16) uint32_t Sw[7680];
    char* smem = (char*)Sw;

    const int tid  = threadIdx.x;
    const int lane = tid & 31, wid = tid >> 5;
    const int wm = wid & 3, wn = wid >> 2;
    const int m0 = blockIdx.y * 128, n0 = blockIdx.x * 64, bz = blockIdx.z;
    const int lr = lane >> 2, lc = lane & 3;

    const __nv_bfloat16 *Ah, *Al, *Bh, *Bl;
    resolve_pair(aid, Ah, Al);
    resolve_pair(bid, Bh, Bl);
    float* C = (cid == 0) ? Cext : (cid == 1 ? g_xz : g_xdbl);

    const size_t abase = (size_t)bz * strA + (size_t)m0 * lda;
    const size_t bbase = (size_t)bz * strB;

    float acc[2][4][4];
#pragma unroll
    for (int mf = 0; mf < 2; mf++)
#pragma unroll
        for (int nf = 0; nf < 4; nf++)
#pragma unroll
            for (int i = 0; i < 4; i++) acc[mf][nf][i] = 0.f;

    const int nst = K >> 5;
    for (int s = 0; s < nst; s++) {
        const int kg = s << 5;
        __syncthreads();
        // A tile: 128 rows x 32 k, hi+lo (512 16B-chunks each -> 2 iters/thread)
#pragma unroll
        for (int i = 0; i < 2; i++) {
            const int c = tid + (i << 8);
            const int r = c >> 2, o = (c & 3) << 3;
            const size_t g = abase + (size_t)r * lda + kg + o;
            *(uint4*)(smem + r * 80 + o * 2)         = *(const uint4*)(Ah + g);
            *(uint4*)(smem + 10240 + r * 80 + o * 2) = *(const uint4*)(Al + g);
        }
        // B tile: 64 rows x 32 k, hi+lo, guarded
        {
            const int r = tid >> 2, o = (tid & 3) << 3;
            const int gn = n0 + r;
            uint4 vh = make_uint4(0u, 0u, 0u, 0u), vl = vh;
            if (gn < Ncols) {
                const size_t g = bbase + (size_t)gn * ldb + kg + o;
                vh = *(const uint4*)(Bh + g);
                vl = *(const uint4*)(Bl + g);
            }
            *(uint4*)(smem + 20480 + r * 80 + o * 2) = vh;
            *(uint4*)(smem + 25600 + r * 80 + o * 2) = vl;
        }
        __syncthreads();

#pragma unroll
        for (int kk = 0; kk < 2; kk++) {
            const int kw = kk * 8 + lc;
            uint32_t ah[2][4], al[2][4], bh[4][2], bl[4][2];
#pragma unroll
            for (int mf = 0; mf < 2; mf++) {
                const int r0 = wm * 32 + mf * 16 + lr;
                ah[mf][0] = Sw[r0 * 20 + kw];
                ah[mf][1] = Sw[(r0 + 8) * 20 + kw];
                ah[mf][2] = Sw[r0 * 20 + kw + 4];
                ah[mf][3] = Sw[(r0 + 8) * 20 + kw + 4];
                al[mf][0] = Sw[2560 + r0 * 20 + kw];
                al[mf][1] = Sw[2560 + (r0 + 8) * 20 + kw];
                al[mf][2] = Sw[2560 + r0 * 20 + kw + 4];
                al[mf][3] = Sw[2560 + (r0 + 8) * 20 + kw + 4];
            }
#pragma unroll
            for (int nf = 0; nf < 4; nf++) {
                const int n = wn * 32 + nf * 8 + lr;
                bh[nf][0] = Sw[5120 + n * 20 + kw];
                bh[nf][1] = Sw[5120 + n * 20 + kw + 4];
                bl[nf][0] = Sw[6400 + n * 20 + kw];
                bl[nf][1] = Sw[6400 + n * 20 + kw + 4];
            }
#pragma unroll
            for (int mf = 0; mf < 2; mf++)
#pragma unroll
                for (int nf = 0; nf < 4; nf++) {
                    MMA_BF16(acc[mf][nf], ah[mf], bh[nf]);
                    MMA_BF16(acc[mf][nf], ah[mf], bl[nf]);
                    MMA_BF16(acc[mf][nf], al[mf], bh[nf]);
                }
        }
    }

    // epilogue: direct float2 stores (c0,c1)->(r,c), (c2,c3)->(r+8,c)
#pragma unroll
    for (int mf = 0; mf < 2; mf++) {
        const int r0 = m0 + wm * 32 + mf * 16 + lr;
#pragma unroll
        for (int nf = 0; nf < 4; nf++) {
            const int c0 = n0 + wn * 32 + nf * 8 + lc * 2;
            if (c0 < Ncols) {
                float v0 = acc[mf][nf][0], v1 = acc[mf][nf][1];
                float v2 = acc[mf][nf][2], v3 = acc[mf][nf][3];
                if (epi == 1) {
                    const float b0 = bias[c0], b1 = bias[c0 + 1];
                    v0 += b0; v1 += b1; v2 += b0; v3 += b1;
                    v0 = (v0 > 20.f) ? v0 : log1pf(expf(v0));
                    v1 = (v1 > 20.f) ? v1 : log1pf(expf(v1));
                    v2 = (v2 > 20.f) ? v2 : log1pf(expf(v2));
                    v3 = (v3 > 20.f) ? v3 : log1pf(expf(v3));
                }
                float2* p0 = (float2*)&C[(size_t)bz * strC + (size_t)r0 * ldc + c0];
                float2* p1 = (float2*)&C[(size_t)bz * strC + (size_t)(r0 + 8) * ldc + c0];
                *p0 = make_float2(v0, v1);
                *p1 = make_float2(v2, v3);
            }
        }
    }
}

// ================= fp32 -> bf16 hi/lo split =================
__global__ void __launch_bounds__(256) cvt_split(
    const float* __restrict__ Sext, int sid, int pid, long long n)
{
    const float* S = (sid == 0) ? Sext : (sid == 1 ? g_xc : (sid == 2 ? g_zt : g_xdbl));
    __nv_bfloat16 *H, *L;
    resolve_pair_m(pid, H, L);
    const long long i = ((long long)blockIdx.x * 256 + threadIdx.x) * 4;
    if (i >= n) return;
    const float4 v = *(const float4*)(S + i);
    __nv_bfloat16 h0 = __float2bfloat16(v.x); float l0 = v.x - __bfloat162float(h0);
    __nv_bfloat16 h1 = __float2bfloat16(v.y); float l1 = v.y - __bfloat162float(h1);
    __nv_bfloat16 h2 = __float2bfloat16(v.z); float l2 = v.z - __bfloat162float(h2);
    __nv_bfloat16 h3 = __float2bfloat16(v.w); float l3 = v.w - __bfloat162float(h3);
    __nv_bfloat162* Hp = (__nv_bfloat162*)(H + i);
    __nv_bfloat162* Lp = (__nv_bfloat162*)(L + i);
    Hp[0] = __nv_bfloat162(h0, h1);
    Hp[1] = __nv_bfloat162(h2, h3);
    Lp[0] = __nv_bfloat162(__float2bfloat16(l0), __float2bfloat16(l1));
    Lp[1] = __nv_bfloat162(__float2bfloat16(l2), __float2bfloat16(l3));
}

// ================= depthwise causal convs + silu + gate mix =================
__global__ void __launch_bounds__(256) conv_gate_kernel(
    const float* __restrict__ w1, const float* __restrict__ b1,
    const float* __restrict__ w2, const float* __restrict__ b2,
    const float* __restrict__ gates)
{
    __shared__ float xs[32][73];
    const int l0 = blockIdx.x * 64;
    const int d0 = blockIdx.y * 32;
    const int b  = blockIdx.z;
    const int tid = threadIdx.x;

    for (int i = tid; i < 32 * 70; i += 256) {
        const int r = i / 70, c = i % 70;
        const int gl = l0 - 6 + c;
        float v = 0.f;
        if (gl >= 0) v = g_xz[((size_t)(b * E2 + d0 + r)) * LSEQ + gl];
        xs[r][c] = v;
    }
    __syncthreads();

    const float e0 = expf(gates[0]), e1 = expf(gates[1]);
    const float g0 = e0 / (e0 + e1), g1 = e1 / (e0 + e1);

    const int dl = tid & 31;
    const int lg = tid >> 5;
    const int d  = d0 + dl;
    const float w10 = w1[d*4+0], w11 = w1[d*4+1], w12 = w1[d*4+2], w13 = w1[d*4+3];
    const float w20 = w2[d*4+0], w21 = w2[d*4+1], w22 = w2[d*4+2], w23 = w2[d*4+3];
    const float b1v = b1[d], b2v = b2[d];

#pragma unroll
    for (int q = 0; q < 8; q++) {
        const int lloc = lg * 8 + q;
        const int p = lloc + 6;
        float v1 = b1v + w10*xs[dl][p-3] + w11*xs[dl][p-2] + w12*xs[dl][p-1] + w13*xs[dl][p];
        v1 = v1 / (1.f + __expf(-v1));
        float v2 = b2v + w20*xs[dl][p-6] + w21*xs[dl][p-4] + w22*xs[dl][p-2] + w23*xs[dl][p];
        v2 = v2 / (1.f + __expf(-v2));
        g_xc[((size_t)b * LSEQ + (l0 + lloc)) * DI + d] = g0 * v1 + g1 * v2;
    }
}

// ================= z: transpose + silu =================
__global__ void __launch_bounds__(256) zt_kernel()
{
    __shared__ float t[32][33];
    const int l0 = blockIdx.x * 32, d0 = blockIdx.y * 32, b = blockIdx.z;
    const int tx = threadIdx.x & 31, ty = threadIdx.x >> 5;
#pragma unroll
    for (int i = 0; i < 4; i++) {
        const int dr = ty + i * 8;
        t[dr][tx] = g_xz[((size_t)(b * E2 + DI + d0 + dr)) * LSEQ + l0 + tx];
    }
    __syncthreads();
#pragma unroll
    for (int i = 0; i < 4; i++) {
        const int lr = ty + i * 8;
        const float v = t[tx][lr];
        g_zt[((size_t)b * LSEQ + (l0 + lr)) * DI + d0 + tx] = v / (1.f + __expf(-v));
    }
}

// ================= selective scan (+ D skip + silu(z) gating) =================
__global__ void __launch_bounds__(64) scan_kernel(
    const float* __restrict__ A_log,
    const float* __restrict__ Dp)
{
    __shared__ float Bs[32][16];
    __shared__ float Cs[32][16];
    const int b = blockIdx.y;
    const int d = blockIdx.x * 64 + threadIdx.x;
    const float* __restrict__ dltp = g_xz;   // delta alias

    float A[NST], h[NST];
#pragma unroll
    for (int n = 0; n < NST; n++) {
        A[n] = -expf(A_log[d * NST + n]);
        h[n] = 0.f;
    }
    const float Dv = Dp[d];

    for (int t0 = 0; t0 < LSEQ; t0 += 32) {
        __syncthreads();
        for (int i = threadIdx.x; i < 32 * 32; i += 64) {
            const int tl = i >> 5, c = i & 31;
            const float v = g_xdbl[((size_t)b * LSEQ + t0 + tl) * XDB + RNK + c];
            if (c < 16) Bs[tl][c] = v;
            else        Cs[tl][c - 16] = v;
        }
        __syncthreads();
        for (int tl = 0; tl < 32; tl++) {
            const size_t idx = ((size_t)b * LSEQ + t0 + tl) * DI + d;
            const float dlt = dltp[idx];
            const float xv  = g_xc[idx];
            const float dbx = dlt * xv;
            float yy = 0.f;
#pragma unroll
            for (int n = 0; n < NST; n++) {
                const float dA = __expf(dlt * A[n]);
                h[n] = fmaf(h[n], dA, dbx * Bs[tl][n]);
                yy   = fmaf(h[n], Cs[tl][n], yy);
            }
            g_zt[idx] = (yy + Dv * xv) * g_zt[idx];
        }
    }
}

// ================= launch (kernel launches ONLY) =================
extern "C" void kernel_launch(void* const* d_in, const int* in_sizes, int n_in,
                              void* d_out, int out_size)
{
    (void)in_sizes; (void)n_in; (void)out_size;
    const float* hs    = (const float*)d_in[0];
    const float* W_in  = (const float*)d_in[1];
    const float* cw1   = (const float*)d_in[2];
    const float* cb1   = (const float*)d_in[3];
    const float* cw2   = (const float*)d_in[4];
    const float* cb2   = (const float*)d_in[5];
    const float* gts   = (const float*)d_in[6];
    const float* W_x   = (const float*)d_in[7];
    const float* W_dt  = (const float*)d_in[8];
    const float* b_dt  = (const float*)d_in[9];
    const float* A_log = (const float*)d_in[10];
    const float* Dp    = (const float*)d_in[11];
    const float* W_out = (const float*)d_in[12];
    float* out = (float*)d_out;

    auto gblk = [](long long n) { return (unsigned)((n / 4 + 255) / 256); };

    // split weights + input to bf16 hi/lo
    cvt_split<<<gblk((long long)E2 * DM), 256>>>(W_in,  0, PB_WIN,  (long long)E2 * DM);
    cvt_split<<<gblk((long long)BZ * LSEQ * DM), 256>>>(hs, 0, PB_HS, (long long)BZ * LSEQ * DM);
    cvt_split<<<gblk((long long)XDB * DI), 256>>>(W_x,   0, PB_WX,   (long long)XDB * DI);
    cvt_split<<<gblk((long long)DI * RNK), 256>>>(W_dt,  0, PB_WDT,  (long long)DI * RNK);
    cvt_split<<<gblk((long long)DM * DI), 256>>>(W_out,  0, PB_WOUT, (long long)DM * DI);

    // 1) xz[b][e][l] = W_in . hs^T   (M=E2, N=LSEQ per batch, K=DM)
    mm_gemm<<<dim3(LSEQ / 64, E2 / 128, BZ), 256>>>(
        PB_WIN, DM, 0LL,
        PB_HS,  DM, (long long)LSEQ * DM,
        nullptr, 1, LSEQ, (long long)E2 * LSEQ,
        DM, LSEQ, nullptr, 0);

    // 2) convs + gate mix; 2b) silu(z) transpose
    conv_gate_kernel<<<dim3(LSEQ / 64, DI / 32, BZ), 256>>>(cw1, cb1, cw2, cb2, gts);
    zt_kernel<<<dim3(LSEQ / 32, DI / 32, BZ), 256>>>();

    // 3) x_dbl = xc . W_x^T  (M=8192, N=96, K=DI)
    cvt_split<<<gblk((long long)BZ * LSEQ * DI), 256>>>(nullptr, 1, PB_XC, (long long)BZ * LSEQ * DI);
    mm_gemm<<<dim3(2, (BZ * LSEQ) / 128, 1), 256>>>(
        PB_XC, DI, 0LL,
        PB_WX, DI, 0LL,
        nullptr, 2, XDB, 0LL,
        DI, XDB, nullptr, 0);

    // 4) delta = softplus(dt_low . W_dt^T + b_dt)  (M=8192, N=DI, K=RNK) -> alias g_xz
    cvt_split<<<gblk((long long)BZ * LSEQ * XDB), 256>>>(nullptr, 3, PB_XDBL, (long long)BZ * LSEQ * XDB);
    mm_gemm<<<dim3(DI / 64, (BZ * LSEQ) / 128, 1), 256>>>(
        PB_XDBL, XDB, 0LL,
        PB_WDT,  RNK, 0LL,
        nullptr, 1, DI, 0LL,
        RNK, DI, b_dt, 1);

    // 5) selective scan -> y (in place over g_zt)
    scan_kernel<<<dim3(DI / 64, BZ), 64>>>(A_log, Dp);

    // 6) out = y . W_out^T  (M=8192, N=DM, K=DI)
    cvt_split<<<gblk((long long)BZ * LSEQ * DI), 256>>>(nullptr, 2, PB_Y, (long long)BZ * LSEQ * DI);
    mm_gemm<<<dim3(DM / 64, (BZ * LSEQ) / 128, 1), 256>>>(
        PB_Y,    DI, 0LL,
        PB_WOUT, DI, 0LL,
        out, 0, DM, 0LL,
        DI, DM, nullptr, 0);
}